// round 13
// baseline (speedup 1.0000x reference)
#include <cuda_runtime.h>
#include <cuda_fp16.h>
#include <cuda.h>
#include <cstdint>
#include <math.h>

#define TTOK 8192
#define DIMX 1024
#define HIDX 2816
#define NE 8
#define NEX 9          // 8 routed experts + shared expert as expert 8
#define CAP 8192
#define HD (HIDX*DIMX)

#define NSTG 4
#define STAGE_BYTES 49152              // A 256x128B (32KB) + B 128x128B (16KB)
#define SMEM_DYN (NSTG*STAGE_BYTES + 1024)

// ---------------- scratch (static device globals; no allocations) -------------
__device__ __align__(1024) __half g_xs[(size_t)NEX*CAP*DIMX];   // slot-ordered x
__device__ __align__(1024) __half g_wg[(size_t)NEX*HD];
__device__ __align__(1024) __half g_wu[(size_t)NEX*HD];
__device__ __align__(1024) __half g_wd[(size_t)NEX*HD];
__device__ __align__(1024) __half g_h16[(size_t)NEX*CAP*HIDX];  // hidden acts
__device__ __align__(1024) float  g_y[(size_t)NEX*CAP*DIMX];
__device__ int    g_cnt[NEX];
__device__ float  g_twf[NEX*CAP];
__device__ int    g_pos[2*TTOK];
// tensormaps: [0]=gu_A(g_xs) [1]=gu_G [2]=gu_U [3]=dn_A(g_h16) [4]=dn_B(g_wd)
__device__ __align__(64) CUtensorMap g_tmap[5];

// ---------------- device helpers ----------------------------------------------
__device__ __forceinline__ uint32_t sptr(const void* p){
  return (uint32_t)__cvta_generic_to_shared(p);
}
__device__ __forceinline__ void mbar_init(uint32_t a, uint32_t n){
  asm volatile("mbarrier.init.shared.b64 [%0], %1;" :: "r"(a), "r"(n) : "memory");
}
__device__ __forceinline__ void mbar_arrive(uint32_t a){
  asm volatile("mbarrier.arrive.shared.b64 _, [%0];" :: "r"(a) : "memory");
}
__device__ __forceinline__ void mbar_expect(uint32_t a, uint32_t tx){
  asm volatile("mbarrier.arrive.expect_tx.shared.b64 _, [%0], %1;" :: "r"(a), "r"(tx) : "memory");
}
__device__ __forceinline__ void mbar_wait(uint32_t a, uint32_t parity){
  uint32_t done;
  asm volatile(
    "{\n\t.reg .pred p;\n\t"
    "mbarrier.try_wait.parity.acquire.cta.shared::cta.b64 p, [%1], %2;\n\t"
    "selp.b32 %0, 1, 0, p;\n\t}"
    : "=r"(done) : "r"(a), "r"(parity) : "memory");
  if (!done){
    asm volatile(
      "{\n\t.reg .pred P1;\n\t"
      "WL_%=:\n\t"
      "mbarrier.try_wait.parity.acquire.cta.shared::cta.b64 P1, [%0], %1, 0x989680;\n\t"
      "@P1 bra.uni WD_%=;\n\t"
      "bra.uni WL_%=;\n\t"
      "WD_%=:\n\t}"
      :: "r"(a), "r"(parity) : "memory");
  }
}
__device__ __forceinline__ void tma2d(uint32_t dst, const CUtensorMap* tm,
                                      int cx, int cy, uint32_t bar){
  asm volatile(
    "cp.async.bulk.tensor.2d.shared::cta.global.tile.mbarrier::complete_tx::bytes "
    "[%0], [%1, {%2, %3}], [%4];"
    :: "r"(dst), "l"(tm), "r"(cx), "r"(cy), "r"(bar) : "memory");
}
__device__ __forceinline__ void ldm4(uint32_t &r0,uint32_t &r1,uint32_t &r2,uint32_t &r3,uint32_t addr){
  asm volatile("ldmatrix.sync.aligned.m8n8.x4.shared.b16 {%0,%1,%2,%3}, [%4];\n"
    : "=r"(r0),"=r"(r1),"=r"(r2),"=r"(r3) : "r"(addr));
}
__device__ __forceinline__ void mma16816(float&d0,float&d1,float&d2,float&d3,
   uint32_t a0,uint32_t a1,uint32_t a2,uint32_t a3,uint32_t b0,uint32_t b1){
  asm volatile("mma.sync.aligned.m16n8k16.row.col.f32.f16.f16.f32 "
    "{%0,%1,%2,%3},{%4,%5,%6,%7},{%8,%9},{%0,%1,%2,%3};\n"
    : "+f"(d0),"+f"(d1),"+f"(d2),"+f"(d3)
    : "r"(a0),"r"(a1),"r"(a2),"r"(a3),"r"(b0),"r"(b1));
}
// silu via single-MUFU tanh.approx: x*sigmoid(x), sigmoid(x)=0.5*tanh(0.5x)+0.5
__device__ __forceinline__ float silu_fast(float x){
  float t;
  asm("tanh.approx.f32 %0, %1;" : "=f"(t) : "f"(0.5f*x));
  return x * fmaf(0.5f, t, 0.5f);
}
// SW128 swizzled smem byte offset for row r (128B rows), 16B chunk c
__device__ __forceinline__ uint32_t swoff(int r, int c){
  return (uint32_t)(r*128 + ((c ^ (r&7))<<4));
}

// ---------------- conversion helper --------------------------------------------
__device__ __forceinline__ void cvt4(__half* dst, const float* __restrict__ src, size_t i){
  float4 v = reinterpret_cast<const float4*>(src)[i];
  __half2* d2 = reinterpret_cast<__half2*>(dst) + 2*i;
  d2[0] = __floats2half2_rn(v.x, v.y);
  d2[1] = __floats2half2_rn(v.z, v.w);
}

// ---------------- cvt gate/up weights + init ------------------------------------
__global__ void cvt_all(const float* __restrict__ gw, const float* __restrict__ uw,
                        const float* __restrict__ sg, const float* __restrict__ su){
  size_t j = (size_t)blockIdx.x*blockDim.x + threadIdx.x;  // float4 idx within tensor
  const size_t Q = (size_t)NE*HD/4;
  if (blockIdx.y == 0){
    if (j < Q) cvt4(g_wg, gw, j);
    else       cvt4(g_wg + (size_t)NE*HD, sg, j-Q);
    // fold init here (once, seg 0)
    if (j < NE)  g_cnt[j] = 0;
    if (j == NE) g_cnt[NE] = TTOK;
    if (j < TTOK) g_twf[NE*CAP+j] = 1.0f;
  } else {
    if (j < Q) cvt4(g_wu, uw, j);
    else       cvt4(g_wu + (size_t)NE*HD, su, j-Q);
  }
}

// ---------------- router: fp64 logit accumulation -> build-stable selection ----
__global__ void router_k(const float* __restrict__ x, const float* __restrict__ rw,
                         const float* __restrict__ eb){
  int t = blockIdx.x*8 + (threadIdx.x>>5);
  int lane = threadIdx.x & 31;
  if (t >= TTOK) return;
  const float* xr = x + (size_t)t*DIMX;
  double acc[NE];
  #pragma unroll
  for (int e=0;e<NE;e++) acc[e]=0.0;
  for (int k = lane; k < DIMX; k += 32){
    double xv = (double)xr[k];
    #pragma unroll
    for (int e=0;e<NE;e++) acc[e] = fma(xv, (double)rw[e*DIMX+k], acc[e]);
  }
  #pragma unroll
  for (int e=0;e<NE;e++){
    #pragma unroll
    for (int o=16;o>0;o>>=1) acc[e] += __shfl_xor_sync(0xffffffffu, acc[e], o);
  }
  if (lane==0){
    double s[NE];
    #pragma unroll
    for (int e=0;e<NE;e++){
      double l = acc[e] + (double)eb[e];
      s[e] = 1.0 / (1.0 + exp(-l));
    }
    int i0=0;
    #pragma unroll
    for (int e=1;e<NE;e++) if (s[e] > s[i0]) i0=e;
    int i1 = (i0==0)?1:0;
    #pragma unroll
    for (int e=0;e<NE;e++) if (e!=i0 && s[e] > s[i1]) i1=e;
    double inv = 1.0 / (s[i0]+s[i1]+1e-6);
    int p0 = atomicAdd(&g_cnt[i0], 1);
    g_twf[i0*CAP+p0]=(float)(s[i0]*inv); g_pos[2*t]   = i0*CAP+p0;
    int p1 = atomicAdd(&g_cnt[i1], 1);
    g_twf[i1*CAP+p1]=(float)(s[i1]*inv); g_pos[2*t+1] = i1*CAP+p1;
  }
}

// ---------------- scatter ------------------------------------------------------
__global__ void scatter_x(const float* __restrict__ x){
  int t = blockIdx.x;
  int c = threadIdx.x;         // 128 threads, 8 halves each
  const float4* xr = reinterpret_cast<const float4*>(x + (size_t)t*DIMX) + 2*c;
  float4 v0 = xr[0], v1 = xr[1];
  __half2 h[4] = { __floats2half2_rn(v0.x,v0.y), __floats2half2_rn(v0.z,v0.w),
                   __floats2half2_rn(v1.x,v1.y), __floats2half2_rn(v1.z,v1.w) };
  uint4 pack = *reinterpret_cast<uint4*>(h);
  int p0 = g_pos[2*t], p1 = g_pos[2*t+1], ps = NE*CAP + t;
  uint4* base = reinterpret_cast<uint4*>(g_xs);
  base[(size_t)p0*128 + c] = pack;
  base[(size_t)p1*128 + c] = pack;
  base[(size_t)ps*128 + c] = pack;
}

// =============== GEMM 1 (TMA): hidden = silu(X Gᵀ) * (X Uᵀ) ===================
// ROUND-7 VALIDATED CONFIG: BM=256, B tile = 64 gate + 64 up, BK=64;
// warps 4m x 2n; 4-stage TMA; occupancy 1. Extra blocks (y==44) convert
// down-weights fp32->fp16 riding the idle DRAM pipe.
__global__ __launch_bounds__(256,1) void gemm_gateup(const float* __restrict__ dw,
                                                     const float* __restrict__ sd){
  extern __shared__ char smraw[];
  __shared__ __align__(8) uint64_t full[NSTG], empty[NSTG];
  if (blockIdx.y == HIDX/64){
    // embedded down-weight conversion: gridDim.x=32, z=9 -> 288 blocks x 256 thr;
    // T = 288*256*88 float4 exactly (full coverage, coalesced).
    const size_t Q = (size_t)NE*HD/4, T = (size_t)NEX*HD/4;
    const size_t NB = (size_t)(CAP/256)*NEX;           // 288 blocks
    const size_t b  = (size_t)blockIdx.z*(CAP/256) + blockIdx.x;
    for (size_t j = b*256 + threadIdx.x; j < T; j += NB*256){
      if (j < Q) cvt4(g_wd, dw, j);
      else       cvt4(g_wd + (size_t)NE*HD, sd, j-Q);
    }
    return;
  }
  const int e = blockIdx.z;
  const int cntE = g_cnt[e];
  const int rowBase = blockIdx.x*256;
  if (rowBase >= cntE) return;
  const int nBase = blockIdx.y*64;
  const int tid = threadIdx.x, lane = tid&31, warp = tid>>5;
  const int wm = warp>>1, wn = warp&1;
  const uint32_t base = (sptr(smraw)+1023u) & ~1023u;
  const int KT = DIMX/64;   // 16

  if (tid==0){
    #pragma unroll
    for (int s=0;s<NSTG;s++){ mbar_init(sptr(&full[s]),1); mbar_init(sptr(&empty[s]),256); }
    asm volatile("fence.mbarrier_init.release.cluster;" ::: "memory");
  }
  __syncthreads();

  auto issue = [&](int ld){
    uint32_t sa = base + (ld%NSTG)*STAGE_BYTES;
    uint32_t bar = sptr(&full[ld%NSTG]);
    mbar_expect(bar, STAGE_BYTES);
    tma2d(sa,            &g_tmap[0], ld*64, e*CAP + rowBase, bar);
    tma2d(sa+32768,      &g_tmap[1], ld*64, e*HIDX + nBase,  bar);
    tma2d(sa+32768+8192, &g_tmap[2], ld*64, e*HIDX + nBase,  bar);
  };
  if (tid==0){ issue(0); issue(1); issue(2); }

  float acc[4][8][4];
  #pragma unroll
  for (int i=0;i<4;i++)
    #pragma unroll
    for (int j=0;j<8;j++)
      #pragma unroll
      for (int k=0;k<4;k++) acc[i][j][k]=0.f;

  for (int kt=0; kt<KT; ++kt){
    const int s = kt%NSTG;
    if (tid==0){
      int ld = kt + (NSTG-1);
      if (ld < KT){
        if (ld >= NSTG) mbar_wait(sptr(&empty[ld%NSTG]), ((ld/NSTG)-1)&1);
        issue(ld);
      }
    }
    mbar_wait(sptr(&full[s]), (kt/NSTG)&1);
    const uint32_t bA = base + s*STAGE_BYTES;
    const uint32_t bB = bA + 32768;
    #pragma unroll
    for (int ks=0; ks<4; ++ks){
      uint32_t a[4][4];
      #pragma unroll
      for (int mt=0; mt<4; ++mt){
        int r = wm*64 + mt*16 + (lane&15);
        ldm4(a[mt][0],a[mt][1],a[mt][2],a[mt][3], bA + swoff(r, ks*2 + (lane>>4)));
      }
      uint32_t b[4][4];   // j 0..1: gate, j 2..3: up
      #pragma unroll
      for (int j=0; j<4; ++j){
        int r = ((j>>1)<<6) + wn*32 + (j&1)*16 + (lane&7) + ((lane>>4)<<3);
        ldm4(b[j][0],b[j][1],b[j][2],b[j][3], bB + swoff(r, ks*2 + ((lane>>3)&1)));
      }
      #pragma unroll
      for (int mt=0; mt<4; ++mt){
        #pragma unroll
        for (int nt=0; nt<8; ++nt){   // nt 0..3 gate, 4..7 up
          int j = nt>>1, p = (nt&1)*2;
          mma16816(acc[mt][nt][0],acc[mt][nt][1],acc[mt][nt][2],acc[mt][nt][3],
                   a[mt][0],a[mt][1],a[mt][2],a[mt][3], b[j][p], b[j][p+1]);
        }
      }
    }
    mbar_arrive(sptr(&empty[s]));
  }

  // epilogue: silu(gate)*up -> fp16 hidden (tanh.approx: 1 MUFU per element)
  const int r0 = lane>>2, c0 = (lane&3)*2;
  #pragma unroll
  for (int mt=0; mt<4; ++mt){
    #pragma unroll
    for (int hh=0; hh<2; ++hh){
      int slot = rowBase + wm*64 + mt*16 + r0 + hh*8;
      __half* hrow = g_h16 + ((size_t)e*CAP + slot)*HIDX + nBase + wn*32;
      #pragma unroll
      for (int nt=0; nt<4; ++nt){
        float g0 = acc[mt][nt][hh*2+0],   g1 = acc[mt][nt][hh*2+1];
        float u0 = acc[mt][nt+4][hh*2+0], u1 = acc[mt][nt+4][hh*2+1];
        float h0 = silu_fast(g0)*u0;
        float h1 = silu_fast(g1)*u1;
        *reinterpret_cast<__half2*>(hrow + nt*8 + c0) = __floats2half2_rn(h0,h1);
      }
    }
  }
}

// =============== GEMM 2 (TMA): y[e][slot] = w * (hidden Dᵀ) ====================
// ROUND-7 VALIDATED CONFIG: BM=256, BN=128, BK=64; warps 4m x 2n; 4-stage TMA;
// occupancy 1; dense g_y stores.
__global__ __launch_bounds__(256,1) void gemm_down(){
  extern __shared__ char smraw[];
  __shared__ __align__(8) uint64_t full[NSTG], empty[NSTG];
  const int e = blockIdx.z;
  const int cntE = g_cnt[e];
  const int rowBase = blockIdx.x*256;
  if (rowBase >= cntE) return;
  const int nBase = blockIdx.y*128;
  const int tid = threadIdx.x, lane = tid&31, warp = tid>>5;
  const int wm = warp>>1, wn = warp&1;
  const uint32_t base = (sptr(smraw)+1023u) & ~1023u;
  const int KT = HIDX/64;   // 44

  if (tid==0){
    #pragma unroll
    for (int s=0;s<NSTG;s++){ mbar_init(sptr(&full[s]),1); mbar_init(sptr(&empty[s]),256); }
    asm volatile("fence.mbarrier_init.release.cluster;" ::: "memory");
  }
  __syncthreads();

  auto issue = [&](int ld){
    uint32_t sa = base + (ld%NSTG)*STAGE_BYTES;
    uint32_t bar = sptr(&full[ld%NSTG]);
    mbar_expect(bar, STAGE_BYTES);
    tma2d(sa,       &g_tmap[3], ld*64, e*CAP + rowBase, bar);
    tma2d(sa+32768, &g_tmap[4], ld*64, e*DIMX + nBase,  bar);
  };
  if (tid==0){ issue(0); issue(1); issue(2); }

  float acc[4][8][4];
  #pragma unroll
  for (int i=0;i<4;i++)
    #pragma unroll
    for (int j=0;j<8;j++)
      #pragma unroll
      for (int k=0;k<4;k++) acc[i][j][k]=0.f;

  for (int kt=0; kt<KT; ++kt){
    const int s = kt%NSTG;
    if (tid==0){
      int ld = kt + (NSTG-1);
      if (ld < KT){
        if (ld >= NSTG) mbar_wait(sptr(&empty[ld%NSTG]), ((ld/NSTG)-1)&1);
        issue(ld);
      }
    }
    mbar_wait(sptr(&full[s]), (kt/NSTG)&1);
    const uint32_t bA = base + s*STAGE_BYTES;
    const uint32_t bB = bA + 32768;
    #pragma unroll
    for (int ks=0; ks<4; ++ks){
      uint32_t a[4][4];
      #pragma unroll
      for (int mt=0; mt<4; ++mt){
        int r = wm*64 + mt*16 + (lane&15);
        ldm4(a[mt][0],a[mt][1],a[mt][2],a[mt][3], bA + swoff(r, ks*2 + (lane>>4)));
      }
      uint32_t b[4][4];
      #pragma unroll
      for (int j=0; j<4; ++j){
        int r = wn*64 + j*16 + (lane&7) + ((lane>>4)<<3);
        ldm4(b[j][0],b[j][1],b[j][2],b[j][3], bB + swoff(r, ks*2 + ((lane>>3)&1)));
      }
      #pragma unroll
      for (int mt=0; mt<4; ++mt){
        #pragma unroll
        for (int nt=0; nt<8; ++nt){
          int j = nt>>1, p = (nt&1)*2;
          mma16816(acc[mt][nt][0],acc[mt][nt][1],acc[mt][nt][2],acc[mt][nt][3],
                   a[mt][0],a[mt][1],a[mt][2],a[mt][3], b[j][p], b[j][p+1]);
        }
      }
    }
    mbar_arrive(sptr(&empty[s]));
  }

  // epilogue: scale by routing weight, dense store into g_y
  const int r0 = lane>>2, c0 = (lane&3)*2;
  #pragma unroll
  for (int mt=0; mt<4; ++mt){
    #pragma unroll
    for (int hh=0; hh<2; ++hh){
      int slot = rowBase + wm*64 + mt*16 + r0 + hh*8;
      float w = g_twf[e*CAP+slot];
      float* yrow = g_y + ((size_t)e*CAP + slot)*DIMX + nBase + wn*64;
      #pragma unroll
      for (int nt=0; nt<8; ++nt){
        float2 v = make_float2(acc[mt][nt][hh*2+0]*w, acc[mt][nt][hh*2+1]*w);
        *reinterpret_cast<float2*>(yrow + nt*8 + c0) = v;
      }
    }
  }
}

// ---------------- gather: out[t] = y[pos0] + y[pos1] + y[shared] --------------
__global__ void gather_k(float4* __restrict__ out){
  int i = blockIdx.x*blockDim.x + threadIdx.x;
  int t = i >> 8;
  int c = i & 255;
  const float4* Y = reinterpret_cast<const float4*>(g_y);
  float4 a = Y[(size_t)g_pos[2*t]  *256 + c];
  float4 b = Y[(size_t)g_pos[2*t+1]*256 + c];
  float4 s = Y[((size_t)NE*CAP + t)*256 + c];
  out[i] = make_float4(a.x+b.x+s.x, a.y+b.y+s.y, a.z+b.z+s.z, a.w+b.w+s.w);
}

// ---------------- host-side tensormap setup -----------------------------------
typedef CUresult (*EncodeFn)(CUtensorMap*, CUtensorMapDataType, cuuint32_t, void*,
                             const cuuint64_t*, const cuuint64_t*, const cuuint32_t*,
                             const cuuint32_t*, CUtensorMapInterleave, CUtensorMapSwizzle,
                             CUtensorMapL2promotion, CUtensorMapFloatOOBfill);

static void encode2d(EncodeFn fn, CUtensorMap* tm, void* ptr,
                     uint64_t cols, uint64_t rows, uint32_t boxc, uint32_t boxr){
  cuuint64_t dims[2]    = { cols, rows };
  cuuint64_t strides[1] = { cols * 2 };
  cuuint32_t box[2]     = { boxc, boxr };
  cuuint32_t estr[2]    = { 1, 1 };
  fn(tm, CU_TENSOR_MAP_DATA_TYPE_FLOAT16, 2, ptr, dims, strides, box, estr,
     CU_TENSOR_MAP_INTERLEAVE_NONE, CU_TENSOR_MAP_SWIZZLE_128B,
     CU_TENSOR_MAP_L2_PROMOTION_L2_128B, CU_TENSOR_MAP_FLOAT_OOB_FILL_NONE);
}

extern "C" void kernel_launch(void* const* d_in, const int* in_sizes, int n_in,
                              void* d_out, int out_size){
  const float* x  = (const float*)d_in[0];
  const float* rw = (const float*)d_in[1];
  const float* eb = (const float*)d_in[2];
  const float* gw = (const float*)d_in[3];
  const float* uw = (const float*)d_in[4];
  const float* dw = (const float*)d_in[5];
  const float* sg = (const float*)d_in[6];
  const float* su = (const float*)d_in[7];
  const float* sd = (const float*)d_in[8];
  float* out = (float*)d_out;
  (void)in_sizes; (void)n_in; (void)out_size;

  static bool setup_done = false;
  if (!setup_done){
    cudaFuncSetAttribute(gemm_gateup, cudaFuncAttributeMaxDynamicSharedMemorySize, SMEM_DYN);
    cudaFuncSetAttribute(gemm_down,   cudaFuncAttributeMaxDynamicSharedMemorySize, SMEM_DYN);
    void* fn = nullptr;
    cudaDriverEntryPointQueryResult qr;
    cudaGetDriverEntryPoint("cuTensorMapEncodeTiled", &fn, cudaEnableDefault, &qr);
    EncodeFn enc = (EncodeFn)fn;
    void *p_xs, *p_wg, *p_wu, *p_wd, *p_h;
    cudaGetSymbolAddress(&p_xs, g_xs);
    cudaGetSymbolAddress(&p_wg, g_wg);
    cudaGetSymbolAddress(&p_wu, g_wu);
    cudaGetSymbolAddress(&p_wd, g_wd);
    cudaGetSymbolAddress(&p_h,  g_h16);
    static CUtensorMap h_tm[5];
    encode2d(enc, &h_tm[0], p_xs, DIMX, (uint64_t)NEX*CAP,  64, 256);  // gu A
    encode2d(enc, &h_tm[1], p_wg, DIMX, (uint64_t)NEX*HIDX, 64, 64);   // gu gate
    encode2d(enc, &h_tm[2], p_wu, DIMX, (uint64_t)NEX*HIDX, 64, 64);   // gu up
    encode2d(enc, &h_tm[3], p_h,  HIDX, (uint64_t)NEX*CAP,  64, 256);  // dn A
    encode2d(enc, &h_tm[4], p_wd, HIDX, (uint64_t)NEX*DIMX, 64, 128);  // dn B
    cudaMemcpyToSymbolAsync(g_tmap, h_tm, 5*sizeof(CUtensorMap), 0,
                            cudaMemcpyHostToDevice, 0);
    setup_done = true;
  }

  // launches: 0=cvt(gu+init) 1=router 2=scatter 3=gateup(+cvt wd) 4=down 5=gather
  {
    unsigned nb = (unsigned)(((size_t)NEX*HD/4 + 255)/256);   // 25344
    cvt_all<<<dim3(nb,2), 256>>>(gw, uw, sg, su);
  }
  router_k<<<TTOK/8, 256>>>(x, rw, eb);
  scatter_x<<<TTOK, 128>>>(x);

  gemm_gateup<<<dim3(CAP/256, HIDX/64 + 1, NEX), 256, SMEM_DYN>>>(dw, sd);
  gemm_down  <<<dim3(CAP/256, DIMX/128, NEX), 256, SMEM_DYN>>>();
  gather_k<<<TTOK*1024/4/256, 256>>>((float4*)out);
}

// round 14
// speedup vs baseline: 1.3504x; 1.3504x over previous
#include <cuda_runtime.h>
#include <cuda_fp16.h>
#include <cuda.h>
#include <cstdint>
#include <math.h>

#define TTOK 8192
#define DIMX 1024
#define HIDX 2816
#define NE 8
#define NEX 9          // 8 routed experts + shared expert as expert 8
#define CAP 8192
#define HD (HIDX*DIMX)

#define NSTG 4
#define STAGE_BYTES 49152              // A 256x128B (32KB) + B 128x128B (16KB)
#define SMEM_DYN (NSTG*STAGE_BYTES + 1024)

// ---------------- scratch (static device globals; no allocations) -------------
__device__ __align__(1024) __half g_xs[(size_t)NEX*CAP*DIMX];   // slot-ordered x
__device__ __align__(1024) __half g_wg[(size_t)NEX*HD];
__device__ __align__(1024) __half g_wu[(size_t)NEX*HD];
__device__ __align__(1024) __half g_wd[(size_t)NEX*HD];
__device__ __align__(1024) __half g_h16[(size_t)NEX*CAP*HIDX];  // hidden acts
__device__ __align__(1024) float  g_y[(size_t)NEX*CAP*DIMX];
__device__ int    g_cnt[NEX];
__device__ float  g_twf[NEX*CAP];
__device__ int    g_pos[2*TTOK];
// tensormaps: [0]=gu_A(g_xs) [1]=gu_G [2]=gu_U [3]=dn_A(g_h16) [4]=dn_B(g_wd)
__device__ __align__(64) CUtensorMap g_tmap[5];

// ---------------- device helpers ----------------------------------------------
__device__ __forceinline__ uint32_t sptr(const void* p){
  return (uint32_t)__cvta_generic_to_shared(p);
}
__device__ __forceinline__ void mbar_init(uint32_t a, uint32_t n){
  asm volatile("mbarrier.init.shared.b64 [%0], %1;" :: "r"(a), "r"(n) : "memory");
}
__device__ __forceinline__ void mbar_arrive(uint32_t a){
  asm volatile("mbarrier.arrive.shared.b64 _, [%0];" :: "r"(a) : "memory");
}
__device__ __forceinline__ void mbar_expect(uint32_t a, uint32_t tx){
  asm volatile("mbarrier.arrive.expect_tx.shared.b64 _, [%0], %1;" :: "r"(a), "r"(tx) : "memory");
}
__device__ __forceinline__ void mbar_wait(uint32_t a, uint32_t parity){
  uint32_t done;
  asm volatile(
    "{\n\t.reg .pred p;\n\t"
    "mbarrier.try_wait.parity.acquire.cta.shared::cta.b64 p, [%1], %2;\n\t"
    "selp.b32 %0, 1, 0, p;\n\t}"
    : "=r"(done) : "r"(a), "r"(parity) : "memory");
  if (!done){
    asm volatile(
      "{\n\t.reg .pred P1;\n\t"
      "WL_%=:\n\t"
      "mbarrier.try_wait.parity.acquire.cta.shared::cta.b64 P1, [%0], %1, 0x989680;\n\t"
      "@P1 bra.uni WD_%=;\n\t"
      "bra.uni WL_%=;\n\t"
      "WD_%=:\n\t}"
      :: "r"(a), "r"(parity) : "memory");
  }
}
__device__ __forceinline__ void tma2d(uint32_t dst, const CUtensorMap* tm,
                                      int cx, int cy, uint32_t bar){
  asm volatile(
    "cp.async.bulk.tensor.2d.shared::cta.global.tile.mbarrier::complete_tx::bytes "
    "[%0], [%1, {%2, %3}], [%4];"
    :: "r"(dst), "l"(tm), "r"(cx), "r"(cy), "r"(bar) : "memory");
}
__device__ __forceinline__ void ldm4(uint32_t &r0,uint32_t &r1,uint32_t &r2,uint32_t &r3,uint32_t addr){
  asm volatile("ldmatrix.sync.aligned.m8n8.x4.shared.b16 {%0,%1,%2,%3}, [%4];\n"
    : "=r"(r0),"=r"(r1),"=r"(r2),"=r"(r3) : "r"(addr));
}
__device__ __forceinline__ void mma16816(float&d0,float&d1,float&d2,float&d3,
   uint32_t a0,uint32_t a1,uint32_t a2,uint32_t a3,uint32_t b0,uint32_t b1){
  asm volatile("mma.sync.aligned.m16n8k16.row.col.f32.f16.f16.f32 "
    "{%0,%1,%2,%3},{%4,%5,%6,%7},{%8,%9},{%0,%1,%2,%3};\n"
    : "+f"(d0),"+f"(d1),"+f"(d2),"+f"(d3)
    : "r"(a0),"r"(a1),"r"(a2),"r"(a3),"r"(b0),"r"(b1));
}
// silu via single-MUFU tanh.approx: x*sigmoid(x), sigmoid(x)=0.5*tanh(0.5x)+0.5
__device__ __forceinline__ float silu_fast(float x){
  float t;
  asm("tanh.approx.f32 %0, %1;" : "=f"(t) : "f"(0.5f*x));
  return x * fmaf(0.5f, t, 0.5f);
}
// pinned fp32 fma: opaque to the compiler -> accumulation order frozen in source,
// immune to fast-math reassociation across builds (determinism at FFMA speed).
__device__ __forceinline__ float ffma_pin(float a, float b, float c){
  float d;
  asm("fma.rn.f32 %0, %1, %2, %3;" : "=f"(d) : "f"(a), "f"(b), "f"(c));
  return d;
}
__device__ __forceinline__ float fadd_pin(float a, float b){
  float d;
  asm("add.f32 %0, %1, %2;" : "=f"(d) : "f"(a), "f"(b));
  return d;
}
// SW128 swizzled smem byte offset for row r (128B rows), 16B chunk c
__device__ __forceinline__ uint32_t swoff(int r, int c){
  return (uint32_t)(r*128 + ((c ^ (r&7))<<4));
}

// ---------------- conversion helper --------------------------------------------
__device__ __forceinline__ void cvt4(__half* dst, const float* __restrict__ src, size_t i){
  float4 v = reinterpret_cast<const float4*>(src)[i];
  __half2* d2 = reinterpret_cast<__half2*>(dst) + 2*i;
  d2[0] = __floats2half2_rn(v.x, v.y);
  d2[1] = __floats2half2_rn(v.z, v.w);
}

// ---------------- cvt gate/up weights + init ------------------------------------
__global__ void cvt_all(const float* __restrict__ gw, const float* __restrict__ uw,
                        const float* __restrict__ sg, const float* __restrict__ su){
  size_t j = (size_t)blockIdx.x*blockDim.x + threadIdx.x;  // float4 idx within tensor
  const size_t Q = (size_t)NE*HD/4;
  if (blockIdx.y == 0){
    if (j < Q) cvt4(g_wg, gw, j);
    else       cvt4(g_wg + (size_t)NE*HD, sg, j-Q);
    // fold init here (once, seg 0)
    if (j < NE)  g_cnt[j] = 0;
    if (j == NE) g_cnt[NE] = TTOK;
    if (j < TTOK) g_twf[NE*CAP+j] = 1.0f;
  } else {
    if (j < Q) cvt4(g_wu, uw, j);
    else       cvt4(g_wu + (size_t)NE*HD, su, j-Q);
  }
}

// ---------------- router: fp32 with asm-pinned accumulation order ---------------
// The k-loop fma chain and shfl tree are opaque/dependent -> identical numerics
// on every build and every call; top-2 selection is stable.
__global__ void router_k(const float* __restrict__ x, const float* __restrict__ rw,
                         const float* __restrict__ eb){
  int t = blockIdx.x*8 + (threadIdx.x>>5);
  int lane = threadIdx.x & 31;
  if (t >= TTOK) return;
  const float* xr = x + (size_t)t*DIMX;
  float acc[NE];
  #pragma unroll
  for (int e=0;e<NE;e++) acc[e]=0.f;
  for (int k = lane; k < DIMX; k += 32){
    float xv = xr[k];
    #pragma unroll
    for (int e=0;e<NE;e++) acc[e] = ffma_pin(xv, rw[e*DIMX+k], acc[e]);
  }
  #pragma unroll
  for (int e=0;e<NE;e++){
    #pragma unroll
    for (int o=16;o>0;o>>=1)
      acc[e] = fadd_pin(acc[e], __shfl_xor_sync(0xffffffffu, acc[e], o));
  }
  if (lane==0){
    float s[NE];
    #pragma unroll
    for (int e=0;e<NE;e++){
      float l = fadd_pin(acc[e], eb[e]);
      s[e] = 1.f / (1.f + __expf(-l));
    }
    int i0=0;
    #pragma unroll
    for (int e=1;e<NE;e++) if (s[e] > s[i0]) i0=e;
    int i1 = (i0==0)?1:0;
    #pragma unroll
    for (int e=0;e<NE;e++) if (e!=i0 && s[e] > s[i1]) i1=e;
    float inv = 1.f / (s[i0]+s[i1]+1e-6f);
    int p0 = atomicAdd(&g_cnt[i0], 1);
    g_twf[i0*CAP+p0]=s[i0]*inv; g_pos[2*t]   = i0*CAP+p0;
    int p1 = atomicAdd(&g_cnt[i1], 1);
    g_twf[i1*CAP+p1]=s[i1]*inv; g_pos[2*t+1] = i1*CAP+p1;
  }
}

// ---------------- scatter ------------------------------------------------------
__global__ void scatter_x(const float* __restrict__ x){
  int t = blockIdx.x;
  int c = threadIdx.x;         // 128 threads, 8 halves each
  const float4* xr = reinterpret_cast<const float4*>(x + (size_t)t*DIMX) + 2*c;
  float4 v0 = xr[0], v1 = xr[1];
  __half2 h[4] = { __floats2half2_rn(v0.x,v0.y), __floats2half2_rn(v0.z,v0.w),
                   __floats2half2_rn(v1.x,v1.y), __floats2half2_rn(v1.z,v1.w) };
  uint4 pack = *reinterpret_cast<uint4*>(h);
  int p0 = g_pos[2*t], p1 = g_pos[2*t+1], ps = NE*CAP + t;
  uint4* base = reinterpret_cast<uint4*>(g_xs);
  base[(size_t)p0*128 + c] = pack;
  base[(size_t)p1*128 + c] = pack;
  base[(size_t)ps*128 + c] = pack;
}

// =============== GEMM 1 (TMA): hidden = silu(X Gᵀ) * (X Uᵀ) ===================
// VALIDATED-STABLE CONFIG: BM=256, B tile = 64 gate + 64 up, BK=64;
// warps 4m x 2n; 4-stage TMA; occupancy 1. Extra blocks (y==44) convert
// down-weights fp32->fp16 riding the idle DRAM pipe.
__global__ __launch_bounds__(256,1) void gemm_gateup(const float* __restrict__ dw,
                                                     const float* __restrict__ sd){
  extern __shared__ char smraw[];
  __shared__ __align__(8) uint64_t full[NSTG], empty[NSTG];
  if (blockIdx.y == HIDX/64){
    // embedded down-weight conversion: gridDim.x=32, z=9 -> 288 blocks x 256 thr;
    // T = 288*256*88 float4 exactly (full coverage, coalesced).
    const size_t Q = (size_t)NE*HD/4, T = (size_t)NEX*HD/4;
    const size_t NB = (size_t)(CAP/256)*NEX;           // 288 blocks
    const size_t b  = (size_t)blockIdx.z*(CAP/256) + blockIdx.x;
    for (size_t j = b*256 + threadIdx.x; j < T; j += NB*256){
      if (j < Q) cvt4(g_wd, dw, j);
      else       cvt4(g_wd + (size_t)NE*HD, sd, j-Q);
    }
    return;
  }
  const int e = blockIdx.z;
  const int cntE = g_cnt[e];
  const int rowBase = blockIdx.x*256;
  if (rowBase >= cntE) return;
  const int nBase = blockIdx.y*64;
  const int tid = threadIdx.x, lane = tid&31, warp = tid>>5;
  const int wm = warp>>1, wn = warp&1;
  const uint32_t base = (sptr(smraw)+1023u) & ~1023u;
  const int KT = DIMX/64;   // 16

  if (tid==0){
    #pragma unroll
    for (int s=0;s<NSTG;s++){ mbar_init(sptr(&full[s]),1); mbar_init(sptr(&empty[s]),256); }
    asm volatile("fence.mbarrier_init.release.cluster;" ::: "memory");
  }
  __syncthreads();

  auto issue = [&](int ld){
    uint32_t sa = base + (ld%NSTG)*STAGE_BYTES;
    uint32_t bar = sptr(&full[ld%NSTG]);
    mbar_expect(bar, STAGE_BYTES);
    tma2d(sa,            &g_tmap[0], ld*64, e*CAP + rowBase, bar);
    tma2d(sa+32768,      &g_tmap[1], ld*64, e*HIDX + nBase,  bar);
    tma2d(sa+32768+8192, &g_tmap[2], ld*64, e*HIDX + nBase,  bar);
  };
  if (tid==0){ issue(0); issue(1); issue(2); }

  float acc[4][8][4];
  #pragma unroll
  for (int i=0;i<4;i++)
    #pragma unroll
    for (int j=0;j<8;j++)
      #pragma unroll
      for (int k=0;k<4;k++) acc[i][j][k]=0.f;

  for (int kt=0; kt<KT; ++kt){
    const int s = kt%NSTG;
    if (tid==0){
      int ld = kt + (NSTG-1);
      if (ld < KT){
        if (ld >= NSTG) mbar_wait(sptr(&empty[ld%NSTG]), ((ld/NSTG)-1)&1);
        issue(ld);
      }
    }
    mbar_wait(sptr(&full[s]), (kt/NSTG)&1);
    const uint32_t bA = base + s*STAGE_BYTES;
    const uint32_t bB = bA + 32768;
    #pragma unroll
    for (int ks=0; ks<4; ++ks){
      uint32_t a[4][4];
      #pragma unroll
      for (int mt=0; mt<4; ++mt){
        int r = wm*64 + mt*16 + (lane&15);
        ldm4(a[mt][0],a[mt][1],a[mt][2],a[mt][3], bA + swoff(r, ks*2 + (lane>>4)));
      }
      uint32_t b[4][4];   // j 0..1: gate, j 2..3: up
      #pragma unroll
      for (int j=0; j<4; ++j){
        int r = ((j>>1)<<6) + wn*32 + (j&1)*16 + (lane&7) + ((lane>>4)<<3);
        ldm4(b[j][0],b[j][1],b[j][2],b[j][3], bB + swoff(r, ks*2 + ((lane>>3)&1)));
      }
      #pragma unroll
      for (int mt=0; mt<4; ++mt){
        #pragma unroll
        for (int nt=0; nt<8; ++nt){   // nt 0..3 gate, 4..7 up
          int j = nt>>1, p = (nt&1)*2;
          mma16816(acc[mt][nt][0],acc[mt][nt][1],acc[mt][nt][2],acc[mt][nt][3],
                   a[mt][0],a[mt][1],a[mt][2],a[mt][3], b[j][p], b[j][p+1]);
        }
      }
    }
    mbar_arrive(sptr(&empty[s]));
  }

  // epilogue: silu(gate)*up -> fp16 hidden (tanh.approx: 1 MUFU per element)
  const int r0 = lane>>2, c0 = (lane&3)*2;
  #pragma unroll
  for (int mt=0; mt<4; ++mt){
    #pragma unroll
    for (int hh=0; hh<2; ++hh){
      int slot = rowBase + wm*64 + mt*16 + r0 + hh*8;
      __half* hrow = g_h16 + ((size_t)e*CAP + slot)*HIDX + nBase + wn*32;
      #pragma unroll
      for (int nt=0; nt<4; ++nt){
        float g0 = acc[mt][nt][hh*2+0],   g1 = acc[mt][nt][hh*2+1];
        float u0 = acc[mt][nt+4][hh*2+0], u1 = acc[mt][nt+4][hh*2+1];
        float h0 = silu_fast(g0)*u0;
        float h1 = silu_fast(g1)*u1;
        *reinterpret_cast<__half2*>(hrow + nt*8 + c0) = __floats2half2_rn(h0,h1);
      }
    }
  }
}

// =============== GEMM 2 (TMA): y[e][slot] = w * (hidden Dᵀ) ====================
// VALIDATED-STABLE CONFIG: BM=256, BN=128, BK=64; warps 4m x 2n; 4-stage TMA;
// occupancy 1; dense g_y stores.
__global__ __launch_bounds__(256,1) void gemm_down(){
  extern __shared__ char smraw[];
  __shared__ __align__(8) uint64_t full[NSTG], empty[NSTG];
  const int e = blockIdx.z;
  const int cntE = g_cnt[e];
  const int rowBase = blockIdx.x*256;
  if (rowBase >= cntE) return;
  const int nBase = blockIdx.y*128;
  const int tid = threadIdx.x, lane = tid&31, warp = tid>>5;
  const int wm = warp>>1, wn = warp&1;
  const uint32_t base = (sptr(smraw)+1023u) & ~1023u;
  const int KT = HIDX/64;   // 44

  if (tid==0){
    #pragma unroll
    for (int s=0;s<NSTG;s++){ mbar_init(sptr(&full[s]),1); mbar_init(sptr(&empty[s]),256); }
    asm volatile("fence.mbarrier_init.release.cluster;" ::: "memory");
  }
  __syncthreads();

  auto issue = [&](int ld){
    uint32_t sa = base + (ld%NSTG)*STAGE_BYTES;
    uint32_t bar = sptr(&full[ld%NSTG]);
    mbar_expect(bar, STAGE_BYTES);
    tma2d(sa,       &g_tmap[3], ld*64, e*CAP + rowBase, bar);
    tma2d(sa+32768, &g_tmap[4], ld*64, e*DIMX + nBase,  bar);
  };
  if (tid==0){ issue(0); issue(1); issue(2); }

  float acc[4][8][4];
  #pragma unroll
  for (int i=0;i<4;i++)
    #pragma unroll
    for (int j=0;j<8;j++)
      #pragma unroll
      for (int k=0;k<4;k++) acc[i][j][k]=0.f;

  for (int kt=0; kt<KT; ++kt){
    const int s = kt%NSTG;
    if (tid==0){
      int ld = kt + (NSTG-1);
      if (ld < KT){
        if (ld >= NSTG) mbar_wait(sptr(&empty[ld%NSTG]), ((ld/NSTG)-1)&1);
        issue(ld);
      }
    }
    mbar_wait(sptr(&full[s]), (kt/NSTG)&1);
    const uint32_t bA = base + s*STAGE_BYTES;
    const uint32_t bB = bA + 32768;
    #pragma unroll
    for (int ks=0; ks<4; ++ks){
      uint32_t a[4][4];
      #pragma unroll
      for (int mt=0; mt<4; ++mt){
        int r = wm*64 + mt*16 + (lane&15);
        ldm4(a[mt][0],a[mt][1],a[mt][2],a[mt][3], bA + swoff(r, ks*2 + (lane>>4)));
      }
      uint32_t b[4][4];
      #pragma unroll
      for (int j=0; j<4; ++j){
        int r = wn*64 + j*16 + (lane&7) + ((lane>>4)<<3);
        ldm4(b[j][0],b[j][1],b[j][2],b[j][3], bB + swoff(r, ks*2 + ((lane>>3)&1)));
      }
      #pragma unroll
      for (int mt=0; mt<4; ++mt){
        #pragma unroll
        for (int nt=0; nt<8; ++nt){
          int j = nt>>1, p = (nt&1)*2;
          mma16816(acc[mt][nt][0],acc[mt][nt][1],acc[mt][nt][2],acc[mt][nt][3],
                   a[mt][0],a[mt][1],a[mt][2],a[mt][3], b[j][p], b[j][p+1]);
        }
      }
    }
    mbar_arrive(sptr(&empty[s]));
  }

  // epilogue: scale by routing weight, dense store into g_y
  const int r0 = lane>>2, c0 = (lane&3)*2;
  #pragma unroll
  for (int mt=0; mt<4; ++mt){
    #pragma unroll
    for (int hh=0; hh<2; ++hh){
      int slot = rowBase + wm*64 + mt*16 + r0 + hh*8;
      float w = g_twf[e*CAP+slot];
      float* yrow = g_y + ((size_t)e*CAP + slot)*DIMX + nBase + wn*64;
      #pragma unroll
      for (int nt=0; nt<8; ++nt){
        float2 v = make_float2(acc[mt][nt][hh*2+0]*w, acc[mt][nt][hh*2+1]*w);
        *reinterpret_cast<float2*>(yrow + nt*8 + c0) = v;
      }
    }
  }
}

// ---------------- gather: out[t] = y[pos0] + y[pos1] + y[shared] --------------
__global__ void gather_k(float4* __restrict__ out){
  int i = blockIdx.x*blockDim.x + threadIdx.x;
  int t = i >> 8;
  int c = i & 255;
  const float4* Y = reinterpret_cast<const float4*>(g_y);
  float4 a = Y[(size_t)g_pos[2*t]  *256 + c];
  float4 b = Y[(size_t)g_pos[2*t+1]*256 + c];
  float4 s = Y[((size_t)NE*CAP + t)*256 + c];
  out[i] = make_float4(a.x+b.x+s.x, a.y+b.y+s.y, a.z+b.z+s.z, a.w+b.w+s.w);
}

// ---------------- host-side tensormap setup -----------------------------------
typedef CUresult (*EncodeFn)(CUtensorMap*, CUtensorMapDataType, cuuint32_t, void*,
                             const cuuint64_t*, const cuuint64_t*, const cuuint32_t*,
                             const cuuint32_t*, CUtensorMapInterleave, CUtensorMapSwizzle,
                             CUtensorMapL2promotion, CUtensorMapFloatOOBfill);

static void encode2d(EncodeFn fn, CUtensorMap* tm, void* ptr,
                     uint64_t cols, uint64_t rows, uint32_t boxc, uint32_t boxr){
  cuuint64_t dims[2]    = { cols, rows };
  cuuint64_t strides[1] = { cols * 2 };
  cuuint32_t box[2]     = { boxc, boxr };
  cuuint32_t estr[2]    = { 1, 1 };
  fn(tm, CU_TENSOR_MAP_DATA_TYPE_FLOAT16, 2, ptr, dims, strides, box, estr,
     CU_TENSOR_MAP_INTERLEAVE_NONE, CU_TENSOR_MAP_SWIZZLE_128B,
     CU_TENSOR_MAP_L2_PROMOTION_L2_128B, CU_TENSOR_MAP_FLOAT_OOB_FILL_NONE);
}

extern "C" void kernel_launch(void* const* d_in, const int* in_sizes, int n_in,
                              void* d_out, int out_size){
  const float* x  = (const float*)d_in[0];
  const float* rw = (const float*)d_in[1];
  const float* eb = (const float*)d_in[2];
  const float* gw = (const float*)d_in[3];
  const float* uw = (const float*)d_in[4];
  const float* dw = (const float*)d_in[5];
  const float* sg = (const float*)d_in[6];
  const float* su = (const float*)d_in[7];
  const float* sd = (const float*)d_in[8];
  float* out = (float*)d_out;
  (void)in_sizes; (void)n_in; (void)out_size;

  static bool setup_done = false;
  if (!setup_done){
    cudaFuncSetAttribute(gemm_gateup, cudaFuncAttributeMaxDynamicSharedMemorySize, SMEM_DYN);
    cudaFuncSetAttribute(gemm_down,   cudaFuncAttributeMaxDynamicSharedMemorySize, SMEM_DYN);
    void* fn = nullptr;
    cudaDriverEntryPointQueryResult qr;
    cudaGetDriverEntryPoint("cuTensorMapEncodeTiled", &fn, cudaEnableDefault, &qr);
    EncodeFn enc = (EncodeFn)fn;
    void *p_xs, *p_wg, *p_wu, *p_wd, *p_h;
    cudaGetSymbolAddress(&p_xs, g_xs);
    cudaGetSymbolAddress(&p_wg, g_wg);
    cudaGetSymbolAddress(&p_wu, g_wu);
    cudaGetSymbolAddress(&p_wd, g_wd);
    cudaGetSymbolAddress(&p_h,  g_h16);
    static CUtensorMap h_tm[5];
    encode2d(enc, &h_tm[0], p_xs, DIMX, (uint64_t)NEX*CAP,  64, 256);  // gu A
    encode2d(enc, &h_tm[1], p_wg, DIMX, (uint64_t)NEX*HIDX, 64, 64);   // gu gate
    encode2d(enc, &h_tm[2], p_wu, DIMX, (uint64_t)NEX*HIDX, 64, 64);   // gu up
    encode2d(enc, &h_tm[3], p_h,  HIDX, (uint64_t)NEX*CAP,  64, 256);  // dn A
    encode2d(enc, &h_tm[4], p_wd, HIDX, (uint64_t)NEX*DIMX, 64, 128);  // dn B
    cudaMemcpyToSymbolAsync(g_tmap, h_tm, 5*sizeof(CUtensorMap), 0,
                            cudaMemcpyHostToDevice, 0);
    setup_done = true;
  }

  // launches: 0=cvt(gu+init) 1=router 2=scatter 3=gateup(+cvt wd) 4=down 5=gather
  {
    unsigned nb = (unsigned)(((size_t)NEX*HD/4 + 255)/256);   // 25344
    cvt_all<<<dim3(nb,2), 256>>>(gw, uw, sg, su);
  }
  router_k<<<TTOK/8, 256>>>(x, rw, eb);
  scatter_x<<<TTOK, 128>>>(x);

  gemm_gateup<<<dim3(CAP/256, HIDX/64 + 1, NEX), 256, SMEM_DYN>>>(dw, sd);
  gemm_down  <<<dim3(CAP/256, DIMX/128, NEX), 256, SMEM_DYN>>>();
  gather_k<<<TTOK*1024/4/256, 256>>>((float4*)out);
}